// round 14
// baseline (speedup 1.0000x reference)
#include <cuda_runtime.h>
#include <cuda_fp16.h>
#include <math.h>
#include <stdint.h>

// ---------------------------------------------------------------------------
// Problem constants
// ---------------------------------------------------------------------------
constexpr int T_     = 1024;
constexpr int B_     = 64;
constexpr int NINP   = 800;
constexpr int NHID   = 1200;
constexpr int NSLOTS = 15;

constexpr int Msz   = T_ * B_;     // 65536 rows (m = t*64 + b)
constexpr int Ksz   = 2 * NINP;    // 1600
constexpr int NP    = 1280;        // NHID padded
constexpr int Erows = Msz + B_;    // 65600 rows of emb_full flattened [t][b]

constexpr int BM = 128, BN = 128, BK = 64;
constexpr int NSTG  = Ksz / BK;    // 25
constexpr int NT    = NP / BN;     // 10
constexpr int MT    = Msz / BM;    // 512
constexpr int NSLOT = NT * 2;      // 20 partial slots

// Output layout
constexpr size_t OFF_MG   = 0;
constexpr size_t OFF_MGN  = (size_t)B_ * T_ * NSLOTS;
constexpr size_t OFF_GATE = OFF_MGN + (size_t)B_ * T_ * NSLOTS;
constexpr size_t OFF_DIST = OFF_GATE + (size_t)B_ * T_;
constexpr size_t OFF_EMB  = OFF_DIST + (size_t)B_ * T_;
constexpr size_t OFF_CUM  = OFF_EMB + (size_t)B_ * NINP;

// Scratch (device globals)
__device__ __half g_E[(size_t)Erows * NINP];    // 105 MB  fp16 emb_full
__device__ __half g_W[(size_t)NP * Ksz];        // 4.1 MB  [n][k], BN folded, fp16
__device__ float g_rw[4 * NP];                  // wg0, wg1, wd, bias
__device__ float g_part[3 * NSLOT * Msz];       // epilogue partials, m-major
__device__ float g_gate[(size_t)B_ * T_];
__device__ float g_gaten[(size_t)B_ * T_];

// Fast sigmoid: 1/(1+2^(-x*log2e)) via ex2.approx + rcp.approx (2 MUFU ops).
__device__ __forceinline__ float sigmf(float x) {
    float e, r;
    asm("ex2.approx.f32 %0, %1;" : "=f"(e) : "f"(-x * 1.4426950408889634f));
    asm("rcp.approx.f32 %0, %1;" : "=f"(r) : "f"(1.0f + e));
    return r;
}

// ---------------------------------------------------------------------------
// PTX helpers (base sm_103 target: cp.async / ldmatrix / mma.sync)
// ---------------------------------------------------------------------------
__device__ __forceinline__ uint32_t smem_u32(const void* p) {
    uint32_t a;
    asm("{ .reg .u64 t; cvta.to.shared.u64 t, %1; cvt.u32.u64 %0, t; }" : "=r"(a) : "l"(p));
    return a;
}
__device__ __forceinline__ void cpasync16(uint32_t dst, const void* src) {
    asm volatile("cp.async.cg.shared.global [%0], [%1], 16;" :: "r"(dst), "l"(src));
}
#define CP_COMMIT() asm volatile("cp.async.commit_group;" ::: "memory")
#define CP_WAIT(N)  asm volatile("cp.async.wait_group %0;" :: "n"(N) : "memory")

#define LDSM4(r, addr)                                                          \
    asm volatile("ldmatrix.sync.aligned.m8n8.x4.shared.b16 {%0,%1,%2,%3}, [%4];" \
        : "=r"((r)[0]), "=r"((r)[1]), "=r"((r)[2]), "=r"((r)[3]) : "r"(addr))

#define MMA_F16(c, a, b0, b1)                                                   \
    asm volatile("mma.sync.aligned.m16n8k16.row.col.f32.f16.f16.f32 "           \
        "{%0,%1,%2,%3}, {%4,%5,%6,%7}, {%8,%9}, {%0,%1,%2,%3};"                 \
        : "+f"((c)[0]), "+f"((c)[1]), "+f"((c)[2]), "+f"((c)[3])                \
        : "r"((a)[0]), "r"((a)[1]), "r"((a)[2]), "r"((a)[3]),                   \
          "r"(b0), "r"(b1))

// SMEM layout (dynamic):
//   [0, 2048)        : wg0/wg1/wd/bias (4 x 128 floats)
//   [4096, +3*32768) : 3 stages of [A 16K][W 16K]
constexpr int SMO_RW  = 0;
constexpr int SMO_STG = 4096;
constexpr int SZ_A  = BM * 128;              // 16384 (128 rows x 128B)
constexpr int SZ_W  = BN * 128;              // 16384
constexpr int STAGE_SZ = SZ_A + SZ_W;        // 32768
constexpr int SMEM_TOTAL = SMO_STG + 3 * STAGE_SZ;  // 102400 (x2 CTAs <= 228KB)

// prep_kernel block partition
constexpr int PE_BLOCKS = (Erows * (NINP / 4) + 255) / 256;  // 51250
constexpr int PW_BLOCKS = (NP * (Ksz / 2) + 255) / 256;      // 4000
constexpr int TE_BLOCKS = (B_ * NINP + 255) / 256;           // 200
constexpr int PREP_BLOCKS = PE_BLOCKS + PW_BLOCKS + TE_BLOCKS;

// ---------------------------------------------------------------------------
// prep: merged pack_e + pack_w + tail_emb (round-12 version, unchanged).
// ---------------------------------------------------------------------------
__global__ void prep_kernel(const float* __restrict__ emb,
                            const float* __restrict__ emb_last,
                            const float* __restrict__ conv1_w,
                            const float* __restrict__ conv1_b,
                            const float* __restrict__ gamma,
                            const float* __restrict__ beta,
                            const float* __restrict__ mean,
                            const float* __restrict__ var,
                            const float* __restrict__ gate2_w,
                            const float* __restrict__ dist_w,
                            float* __restrict__ out) {
    const int bx = blockIdx.x;
    if (bx < PE_BLOCKS) {
        // ---- pack_e: emb_full -> fp16 (float4 load, single 8B store) ----
        int idx = bx * 256 + threadIdx.x;            // float4 group index
        if (idx >= Erows * (NINP / 4)) return;
        int r = idx / (NINP / 4);
        int k = (idx - r * (NINP / 4)) * 4;
        const float* src = (r < B_) ? (emb_last + (size_t)r * NINP + k)
                                    : (emb + (size_t)(r - B_) * NINP + k);
        float4 v = *(const float4*)src;
        __half2 p0; p0.x = __float2half_rn(v.x); p0.y = __float2half_rn(v.y);
        __half2 p1; p1.x = __float2half_rn(v.z); p1.y = __float2half_rn(v.w);
        uint2 pk;
        pk.x = *(uint32_t*)&p0;
        pk.y = *(uint32_t*)&p1;
        *(reinterpret_cast<uint2*>(g_E) + idx) = pk;   // 8B aligned by idx
    } else if (bx < PE_BLOCKS + PW_BLOCKS) {
        // ---- pack_w: BN-folded fp16 weights + reduction vectors ----
        int idx = (bx - PE_BLOCKS) * 256 + threadIdx.x;   // pair index
        if (idx >= NP * (Ksz / 2)) return;
        int n = idx / (Ksz / 2);
        int k = (idx - n * (Ksz / 2)) * 2;
        float w0 = 0.f, w1 = 0.f;
        if (n < NHID) {
            float scale = gamma[n] * rsqrtf(var[n] + 1e-5f);
            int c = (k < NINP) ? 0 : 1;
            int i = (k < NINP) ? k : k - NINP;
            w0 = conv1_w[(size_t)n * Ksz + i * 2 + c] * scale;
            w1 = conv1_w[(size_t)n * Ksz + (i + 1) * 2 + c] * scale;
        }
        __half2 pw; pw.x = __float2half_rn(w0); pw.y = __float2half_rn(w1);
        reinterpret_cast<__half2*>(g_W)[idx] = pw;

        if (idx < NP) {
            int h = idx;
            float wg0 = 0.f, wg1 = 0.f, wd = 0.f, bz = 0.f;
            if (h < NHID) {
                if (h < 600) wg0 = gate2_w[h]; else wg1 = gate2_w[h];
                wd = dist_w[h];
                float scale = gamma[h] * rsqrtf(var[h] + 1e-5f);
                bz = (conv1_b[h] - mean[h]) * scale + beta[h];
            }
            g_rw[0 * NP + h] = wg0;
            g_rw[1 * NP + h] = wg1;
            g_rw[2 * NP + h] = wd;
            g_rw[3 * NP + h] = bz;
        }
    } else {
        // ---- tail_emb: emb_full[-1] copy ----
        int i = (bx - PE_BLOCKS - PW_BLOCKS) * 256 + threadIdx.x;
        if (i < B_ * NINP)
            out[OFF_EMB + i] = emb[(size_t)(T_ - 1) * B_ * NINP + i];
    }
}

// ---------------------------------------------------------------------------
// Templated mainloop (round-9 version, verbatim).
// NILIM compile-time: 8 (full), 6 (last tile wn=0), 0 (last tile wn=1).
// ---------------------------------------------------------------------------
template<int NILIM>
__device__ __forceinline__ void run_mainloop(
    float (&acc)[4][8][4], uint32_t sb, int m0, int n0,
    int tid, int lane, int wm, int wn) {

    auto load_stage = [&](int s, int buf) {
        const int k0 = s * BK;
        const uint32_t base = sb + SMO_STG + buf * STAGE_SZ;
#pragma unroll
        for (int i = 0; i < 16; ++i) {
            int q = tid + i * 128;
            const __half* src;
            uint32_t off;
            if (q < 1024) {                       // A: 128 rows x 8 16B-chunks
                int rr  = q >> 3;
                int cb  = q & 7;
                int k   = k0 + cb * 8;
                int row = m0 + rr + ((k < NINP) ? 0 : B_);
                int kk  = (k < NINP) ? k : (k - NINP);
                src = g_E + (size_t)row * NINP + kk;
                uint32_t o = rr * 128 + cb * 16;
                off = o ^ ((o >> 3) & 0x70);
            } else {                              // W: 128 rows x 8 chunks
                int w   = q - 1024;
                int rr  = w >> 3;
                int cb  = w & 7;
                src = g_W + (size_t)(n0 + rr) * Ksz + k0 + cb * 8;
                uint32_t o = rr * 128 + cb * 16;
                off = SZ_A + (o ^ ((o >> 3) & 0x70));
            }
            cpasync16(base + off, src);
        }
        CP_COMMIT();
    };

    load_stage(0, 0);
    load_stage(1, 1);

    for (int s = 0; s < NSTG; ++s) {
        const int buf = (s < 3) ? s : (s % 3);
        CP_WAIT(1);
        __syncthreads();   // stage s resident; all warps past stage s-1

        if (NILIM > 0) {
            const uint32_t aB = sb + SMO_STG + buf * STAGE_SZ;
            const uint32_t wB = aB + SZ_A;
#pragma unroll
            for (int kt = 0; kt < 4; ++kt) {
                const int kb = kt * 32;
                uint32_t af[4][4];
#pragma unroll
                for (int mi = 0; mi < 4; ++mi) {
                    int row = wm * 64 + mi * 16 + (lane & 15);
                    uint32_t o  = row * 128 + kb + ((lane >> 4) * 16);
                    uint32_t so = o ^ ((o >> 3) & 0x70);
                    LDSM4(af[mi], aB + so);
                }
                const int wrow = wn * 64 + ((lane >> 4) * 8) + (lane & 7);
                const int wkof = ((lane >> 3) & 1) * 16;
                uint32_t bw[2][4];
                {
                    uint32_t ob = (wrow + 0 * 16) * 128 + kb + wkof;
                    LDSM4(bw[0], wB + (ob ^ ((ob >> 3) & 0x70)));
                }
#pragma unroll
                for (int p = 0; p < NILIM / 2; ++p) {
                    int cur = p & 1;
                    if (p + 1 < NILIM / 2) {
                        uint32_t ob = (wrow + (p + 1) * 16) * 128 + kb + wkof;
                        LDSM4(bw[cur ^ 1], wB + (ob ^ ((ob >> 3) & 0x70)));
                    }
#pragma unroll
                    for (int mi = 0; mi < 4; ++mi)
                        MMA_F16(acc[mi][2 * p], af[mi], bw[cur][0], bw[cur][1]);
#pragma unroll
                    for (int mi = 0; mi < 4; ++mi)
                        MMA_F16(acc[mi][2 * p + 1], af[mi], bw[cur][2], bw[cur][3]);
                }
            }
        }
        if (s + 2 < NSTG) load_stage(s + 2, (s + 2) % 3);
        else CP_COMMIT();   // keep group counts consistent for CP_WAIT(1)
    }
}

// ---------------------------------------------------------------------------
// Single-product fp16 HMMA GEMM with fused reduction epilogue (round-9
// version, verbatim: m-major g_part, coalesced-ish epilogue stores).
// ---------------------------------------------------------------------------
__global__ __launch_bounds__(128, 2)
void gemm_kernel() {
    extern __shared__ char smc[];
    const uint32_t sb = smem_u32(smc);
    const int tid  = threadIdx.x;
    const int wid  = tid >> 5;
    const int lane = tid & 31;
    const int wm   = wid & 1;
    const int wn   = wid >> 1;
    const int nt   = blockIdx.x;
    const int n0   = nt * BN;
    const int m0   = blockIdx.y * BM;

    float* sWg0  = (float*)(smc + SMO_RW);
    float* sWg1  = sWg0 + BN;
    float* sWd   = sWg1 + BN;
    float* sBias = sWd + BN;
    for (int i = tid; i < BN; i += 128) {
        sWg0[i]  = g_rw[0 * NP + n0 + i];
        sWg1[i]  = g_rw[1 * NP + n0 + i];
        sWd[i]   = g_rw[2 * NP + n0 + i];
        sBias[i] = g_rw[3 * NP + n0 + i];
    }

    float acc[4][8][4];
#pragma unroll
    for (int a = 0; a < 4; ++a)
#pragma unroll
        for (int b = 0; b < 8; ++b)
#pragma unroll
            for (int c = 0; c < 4; ++c) acc[a][b][c] = 0.f;

    if (nt != NT - 1)      run_mainloop<8>(acc, sb, m0, n0, tid, lane, wm, wn);
    else if (wn == 0)      run_mainloop<6>(acc, sb, m0, n0, tid, lane, wm, wn);
    else                   run_mainloop<0>(acc, sb, m0, n0, tid, lane, wm, wn);

    float rs[4][2][3];
#pragma unroll
    for (int mi = 0; mi < 4; ++mi)
#pragma unroll
        for (int e2 = 0; e2 < 2; ++e2)
            rs[mi][e2][0] = rs[mi][e2][1] = rs[mi][e2][2] = 0.f;

#pragma unroll
    for (int mi = 0; mi < 4; ++mi)
#pragma unroll
        for (int ni = 0; ni < 8; ++ni)
#pragma unroll
            for (int e = 0; e < 4; ++e) {
                int col = wn * 64 + ni * 8 + 2 * (lane & 3) + (e & 1);
                float v = fmaxf(acc[mi][ni][e] + sBias[col], 0.f);
                rs[mi][e >> 1][0] = fmaf(v, sWg0[col], rs[mi][e >> 1][0]);
                rs[mi][e >> 1][1] = fmaf(v, sWg1[col], rs[mi][e >> 1][1]);
                rs[mi][e >> 1][2] = fmaf(v, sWd[col],  rs[mi][e >> 1][2]);
            }

    const int slot = nt * 2 + wn;
#pragma unroll
    for (int mi = 0; mi < 4; ++mi)
#pragma unroll
        for (int e2 = 0; e2 < 2; ++e2)
#pragma unroll
            for (int ch = 0; ch < 3; ++ch) {
                float v = rs[mi][e2][ch];
                v += __shfl_xor_sync(0xffffffffu, v, 1);
                v += __shfl_xor_sync(0xffffffffu, v, 2);
                if ((lane & 3) == 0) {
                    int row = m0 + wm * 64 + mi * 16 + (lane >> 2) + e2 * 8;
                    g_part[((size_t)ch * NSLOT + slot) * Msz + row] = v;
                }
            }
}

// ---------------------------------------------------------------------------
// finalize: combine partials -> gate, gate_next, distances.
// ---------------------------------------------------------------------------
__global__ void finalize_kernel(const float* __restrict__ gate2_b,
                                const float* __restrict__ dist_b,
                                float* __restrict__ out) {
    int m = blockIdx.x * blockDim.x + threadIdx.x;
    if (m >= Msz) return;
    float s0 = 0.f, s1 = 0.f, sd = 0.f;
#pragma unroll
    for (int sl = 0; sl < NSLOT; ++sl) {
        s0 += g_part[(0 * NSLOT + sl) * (size_t)Msz + m];
        s1 += g_part[(1 * NSLOT + sl) * (size_t)Msz + m];
        sd += g_part[(2 * NSLOT + sl) * (size_t)Msz + m];
    }
    int t = m >> 6, b = m & 63;
    int bt = b * T_ + t;
    float gate  = sigmf(s0 + gate2_b[0]);
    float gaten = sigmf(s1 + gate2_b[1]);
    g_gate[bt]  = gate;
    g_gaten[bt] = gaten;
    out[OFF_GATE + bt] = gate;
    out[OFF_DIST + bt] = sd + dist_b[0];
}

// ---------------------------------------------------------------------------
// mg / mgn cumprod + cum[:, -15:] tail. ILP version: all 30 sigmoids are
// computed into registers FIRST (independent -> MUFUs pipeline), then the two
// cumprod chains are pure FMUL chains. Same ops, same order => bit-identical.
// ---------------------------------------------------------------------------
__global__ void mg_cum_kernel(const float* __restrict__ cum_gate, float* __restrict__ out) {
    int idx = blockIdx.x * blockDim.x + threadIdx.x;
    if (idx >= B_ * T_) return;
    int b = idx >> 10, t = idx & (T_ - 1);
    float g  = g_gate[idx];
    float gn = g_gaten[idx];

    // Phase 1: gather gate_hat and compute independent sigmoids.
    float sm[NSLOTS], sn[NSLOTS];
#pragma unroll
    for (int j = 0; j < NSLOTS; ++j) {
        int s = NSLOTS - j + t;
        float gh = (s < NSLOTS) ? cum_gate[b * NSLOTS + s] : g_gate[b * T_ + (s - NSLOTS)];
        sm[j] = sigmf((g  - gh) * 100.f + 5.f);
        sn[j] = sigmf((gn - gh) * 100.f + 5.f);
    }

    // Phase 2: two independent cumprod chains + stores.
    float pm = 1.f, pn = 1.f;
    float* om = out + OFF_MG  + (size_t)idx * NSLOTS;
    float* on = out + OFF_MGN + (size_t)idx * NSLOTS;
#pragma unroll
    for (int j = 0; j < NSLOTS; ++j) {
        pm *= sm[j];
        pn *= sn[j];
        om[j] = pm;
        on[j] = pn;
    }

    if (idx < B_ * NSLOTS) {
        int bb = idx / NSLOTS, j = idx % NSLOTS;
        out[OFF_CUM + idx] = g_gate[bb * T_ + (T_ - NSLOTS) + j];
    }
}

extern "C" void kernel_launch(void* const* d_in, const int* in_sizes, int n_in,
                              void* d_out, int out_size) {
    const float* emb      = (const float*)d_in[0];
    const float* emb_last = (const float*)d_in[1];
    const float* cum_gate = (const float*)d_in[2];
    const float* conv1_w  = (const float*)d_in[3];
    const float* conv1_b  = (const float*)d_in[4];
    const float* bn_gamma = (const float*)d_in[5];
    const float* bn_beta  = (const float*)d_in[6];
    const float* bn_mean  = (const float*)d_in[7];
    const float* bn_var   = (const float*)d_in[8];
    const float* gate2_w  = (const float*)d_in[9];
    const float* gate2_b  = (const float*)d_in[10];
    const float* dist_w   = (const float*)d_in[11];
    const float* dist_b   = (const float*)d_in[12];
    float* out = (float*)d_out;

    cudaFuncSetAttribute(gemm_kernel, cudaFuncAttributeMaxDynamicSharedMemorySize,
                         SMEM_TOTAL);

    prep_kernel<<<PREP_BLOCKS, 256>>>(emb, emb_last, conv1_w, conv1_b, bn_gamma,
                                      bn_beta, bn_mean, bn_var, gate2_w, dist_w, out);
    gemm_kernel<<<dim3(NT, MT), 128, SMEM_TOTAL>>>();
    finalize_kernel<<<Msz / 256, 256>>>(gate2_b, dist_b, out);
    mg_cum_kernel<<<(B_ * T_) / 256, 256>>>(cum_gate, out);
}

// round 15
// speedup vs baseline: 1.0138x; 1.0138x over previous
#include <cuda_runtime.h>
#include <cuda_fp16.h>
#include <math.h>
#include <stdint.h>

// ---------------------------------------------------------------------------
// Problem constants
// ---------------------------------------------------------------------------
constexpr int T_     = 1024;
constexpr int B_     = 64;
constexpr int NINP   = 800;
constexpr int NHID   = 1200;
constexpr int NSLOTS = 15;

constexpr int Msz   = T_ * B_;     // 65536 rows (m = t*64 + b)
constexpr int Ksz   = 2 * NINP;    // 1600
constexpr int NP    = 1280;        // NHID padded
constexpr int Erows = Msz + B_;    // 65600 rows of emb_full flattened [t][b]

constexpr int BM = 128, BN = 128, BK = 64;
constexpr int NSTG  = Ksz / BK;    // 25
constexpr int NT    = NP / BN;     // 10
constexpr int MT    = Msz / BM;    // 512
constexpr int NSLOT = NT * 2;      // 20 partial slots

// Output layout
constexpr size_t OFF_MG   = 0;
constexpr size_t OFF_MGN  = (size_t)B_ * T_ * NSLOTS;
constexpr size_t OFF_GATE = OFF_MGN + (size_t)B_ * T_ * NSLOTS;
constexpr size_t OFF_DIST = OFF_GATE + (size_t)B_ * T_;
constexpr size_t OFF_EMB  = OFF_DIST + (size_t)B_ * T_;
constexpr size_t OFF_CUM  = OFF_EMB + (size_t)B_ * NINP;

// Scratch (device globals)
__device__ __half g_E[(size_t)Erows * NINP];    // 105 MB  fp16 emb_full
__device__ __half g_W[(size_t)NP * Ksz];        // 4.1 MB  [n][k], BN folded, fp16
__device__ float g_rw[4 * NP];                  // wg0, wg1, wd, bias
__device__ float g_part[3 * NSLOT * Msz];       // epilogue partials, m-major
__device__ float g_gate[(size_t)B_ * T_];
__device__ float g_gaten[(size_t)B_ * T_];

// Fast sigmoid: 1/(1+2^(-x*log2e)) via ex2.approx + rcp.approx (2 MUFU ops).
__device__ __forceinline__ float sigmf(float x) {
    float e, r;
    asm("ex2.approx.f32 %0, %1;" : "=f"(e) : "f"(-x * 1.4426950408889634f));
    asm("rcp.approx.f32 %0, %1;" : "=f"(r) : "f"(1.0f + e));
    return r;
}

// ---------------------------------------------------------------------------
// PTX helpers (base sm_103 target: cp.async / ldmatrix / mma.sync)
// ---------------------------------------------------------------------------
__device__ __forceinline__ uint32_t smem_u32(const void* p) {
    uint32_t a;
    asm("{ .reg .u64 t; cvta.to.shared.u64 t, %1; cvt.u32.u64 %0, t; }" : "=r"(a) : "l"(p));
    return a;
}
__device__ __forceinline__ void cpasync16(uint32_t dst, const void* src) {
    asm volatile("cp.async.cg.shared.global [%0], [%1], 16;" :: "r"(dst), "l"(src));
}
#define CP_COMMIT() asm volatile("cp.async.commit_group;" ::: "memory")
#define CP_WAIT(N)  asm volatile("cp.async.wait_group %0;" :: "n"(N) : "memory")

#define LDSM4(r, addr)                                                          \
    asm volatile("ldmatrix.sync.aligned.m8n8.x4.shared.b16 {%0,%1,%2,%3}, [%4];" \
        : "=r"((r)[0]), "=r"((r)[1]), "=r"((r)[2]), "=r"((r)[3]) : "r"(addr))

#define MMA_F16(c, a, b0, b1)                                                   \
    asm volatile("mma.sync.aligned.m16n8k16.row.col.f32.f16.f16.f32 "           \
        "{%0,%1,%2,%3}, {%4,%5,%6,%7}, {%8,%9}, {%0,%1,%2,%3};"                 \
        : "+f"((c)[0]), "+f"((c)[1]), "+f"((c)[2]), "+f"((c)[3])                \
        : "r"((a)[0]), "r"((a)[1]), "r"((a)[2]), "r"((a)[3]),                   \
          "r"(b0), "r"(b1))

// SMEM layout (dynamic):
//   [0, 2048)        : wg0/wg1/wd/bias (4 x 128 floats)
//   [4096, +3*32768) : 3 stages of [A 16K][W 16K]
constexpr int SMO_RW  = 0;
constexpr int SMO_STG = 4096;
constexpr int SZ_A  = BM * 128;              // 16384 (128 rows x 128B)
constexpr int SZ_W  = BN * 128;              // 16384
constexpr int STAGE_SZ = SZ_A + SZ_W;        // 32768
constexpr int SMEM_TOTAL = SMO_STG + 3 * STAGE_SZ;  // 102400 (x2 CTAs <= 228KB)

// prep_kernel block partition. pack_e: each thread handles TWO group-chunks
// (one from each half of the group space) -> 2 independent LDG.128 in flight.
constexpr int PE_GROUPS = Erows * (NINP / 4);                // 13,120,000
constexpr int PE_HALF   = PE_GROUPS / 2;                     // 6,560,000
constexpr int PE_BLOCKS = (PE_HALF + 255) / 256;             // 25625
constexpr int PW_BLOCKS = (NP * (Ksz / 2) + 255) / 256;      // 4000
constexpr int TE_BLOCKS = (B_ * NINP + 255) / 256;           // 200
constexpr int PREP_BLOCKS = PE_BLOCKS + PW_BLOCKS + TE_BLOCKS;

// ---------------------------------------------------------------------------
// prep: merged pack_e (2 chunks/thread, MLP=2) + pack_w + tail_emb.
// ---------------------------------------------------------------------------
__global__ void prep_kernel(const float* __restrict__ emb,
                            const float* __restrict__ emb_last,
                            const float* __restrict__ conv1_w,
                            const float* __restrict__ conv1_b,
                            const float* __restrict__ gamma,
                            const float* __restrict__ beta,
                            const float* __restrict__ mean,
                            const float* __restrict__ var,
                            const float* __restrict__ gate2_w,
                            const float* __restrict__ dist_w,
                            float* __restrict__ out) {
    const int bx = blockIdx.x;
    if (bx < PE_BLOCKS) {
        // ---- pack_e: emb_full -> fp16. Two group-chunks per thread, one in
        // each half of the group space (both halves warp-coalesced). Both
        // LDG.128 issued before any convert/store -> MLP=2.
        int i0 = bx * 256 + threadIdx.x;             // group in first half
        if (i0 >= PE_HALF) return;
        int i1 = i0 + PE_HALF;                       // group in second half

        int r0 = i0 / (NINP / 4), k0 = (i0 - r0 * (NINP / 4)) * 4;
        int r1 = i1 / (NINP / 4), k1 = (i1 - r1 * (NINP / 4)) * 4;
        const float* s0 = (r0 < B_) ? (emb_last + (size_t)r0 * NINP + k0)
                                    : (emb + (size_t)(r0 - B_) * NINP + k0);
        const float* s1 = (r1 < B_) ? (emb_last + (size_t)r1 * NINP + k1)
                                    : (emb + (size_t)(r1 - B_) * NINP + k1);
        float4 v0 = *(const float4*)s0;
        float4 v1 = *(const float4*)s1;

        __half2 a0; a0.x = __float2half_rn(v0.x); a0.y = __float2half_rn(v0.y);
        __half2 a1; a1.x = __float2half_rn(v0.z); a1.y = __float2half_rn(v0.w);
        uint2 p0; p0.x = *(uint32_t*)&a0; p0.y = *(uint32_t*)&a1;
        *(reinterpret_cast<uint2*>(g_E) + i0) = p0;

        __half2 b0; b0.x = __float2half_rn(v1.x); b0.y = __float2half_rn(v1.y);
        __half2 b1; b1.x = __float2half_rn(v1.z); b1.y = __float2half_rn(v1.w);
        uint2 p1; p1.x = *(uint32_t*)&b0; p1.y = *(uint32_t*)&b1;
        *(reinterpret_cast<uint2*>(g_E) + i1) = p1;
    } else if (bx < PE_BLOCKS + PW_BLOCKS) {
        // ---- pack_w: BN-folded fp16 weights + reduction vectors ----
        int idx = (bx - PE_BLOCKS) * 256 + threadIdx.x;   // pair index
        if (idx >= NP * (Ksz / 2)) return;
        int n = idx / (Ksz / 2);
        int k = (idx - n * (Ksz / 2)) * 2;
        float w0 = 0.f, w1 = 0.f;
        if (n < NHID) {
            float scale = gamma[n] * rsqrtf(var[n] + 1e-5f);
            int c = (k < NINP) ? 0 : 1;
            int i = (k < NINP) ? k : k - NINP;
            w0 = conv1_w[(size_t)n * Ksz + i * 2 + c] * scale;
            w1 = conv1_w[(size_t)n * Ksz + (i + 1) * 2 + c] * scale;
        }
        __half2 pw; pw.x = __float2half_rn(w0); pw.y = __float2half_rn(w1);
        reinterpret_cast<__half2*>(g_W)[idx] = pw;

        if (idx < NP) {
            int h = idx;
            float wg0 = 0.f, wg1 = 0.f, wd = 0.f, bz = 0.f;
            if (h < NHID) {
                if (h < 600) wg0 = gate2_w[h]; else wg1 = gate2_w[h];
                wd = dist_w[h];
                float scale = gamma[h] * rsqrtf(var[h] + 1e-5f);
                bz = (conv1_b[h] - mean[h]) * scale + beta[h];
            }
            g_rw[0 * NP + h] = wg0;
            g_rw[1 * NP + h] = wg1;
            g_rw[2 * NP + h] = wd;
            g_rw[3 * NP + h] = bz;
        }
    } else {
        // ---- tail_emb: emb_full[-1] copy ----
        int i = (bx - PE_BLOCKS - PW_BLOCKS) * 256 + threadIdx.x;
        if (i < B_ * NINP)
            out[OFF_EMB + i] = emb[(size_t)(T_ - 1) * B_ * NINP + i];
    }
}

// ---------------------------------------------------------------------------
// Templated mainloop (round-9 version, verbatim).
// NILIM compile-time: 8 (full), 6 (last tile wn=0), 0 (last tile wn=1).
// ---------------------------------------------------------------------------
template<int NILIM>
__device__ __forceinline__ void run_mainloop(
    float (&acc)[4][8][4], uint32_t sb, int m0, int n0,
    int tid, int lane, int wm, int wn) {

    auto load_stage = [&](int s, int buf) {
        const int k0 = s * BK;
        const uint32_t base = sb + SMO_STG + buf * STAGE_SZ;
#pragma unroll
        for (int i = 0; i < 16; ++i) {
            int q = tid + i * 128;
            const __half* src;
            uint32_t off;
            if (q < 1024) {                       // A: 128 rows x 8 16B-chunks
                int rr  = q >> 3;
                int cb  = q & 7;
                int k   = k0 + cb * 8;
                int row = m0 + rr + ((k < NINP) ? 0 : B_);
                int kk  = (k < NINP) ? k : (k - NINP);
                src = g_E + (size_t)row * NINP + kk;
                uint32_t o = rr * 128 + cb * 16;
                off = o ^ ((o >> 3) & 0x70);
            } else {                              // W: 128 rows x 8 chunks
                int w   = q - 1024;
                int rr  = w >> 3;
                int cb  = w & 7;
                src = g_W + (size_t)(n0 + rr) * Ksz + k0 + cb * 8;
                uint32_t o = rr * 128 + cb * 16;
                off = SZ_A + (o ^ ((o >> 3) & 0x70));
            }
            cpasync16(base + off, src);
        }
        CP_COMMIT();
    };

    load_stage(0, 0);
    load_stage(1, 1);

    for (int s = 0; s < NSTG; ++s) {
        const int buf = (s < 3) ? s : (s % 3);
        CP_WAIT(1);
        __syncthreads();   // stage s resident; all warps past stage s-1

        if (NILIM > 0) {
            const uint32_t aB = sb + SMO_STG + buf * STAGE_SZ;
            const uint32_t wB = aB + SZ_A;
#pragma unroll
            for (int kt = 0; kt < 4; ++kt) {
                const int kb = kt * 32;
                uint32_t af[4][4];
#pragma unroll
                for (int mi = 0; mi < 4; ++mi) {
                    int row = wm * 64 + mi * 16 + (lane & 15);
                    uint32_t o  = row * 128 + kb + ((lane >> 4) * 16);
                    uint32_t so = o ^ ((o >> 3) & 0x70);
                    LDSM4(af[mi], aB + so);
                }
                const int wrow = wn * 64 + ((lane >> 4) * 8) + (lane & 7);
                const int wkof = ((lane >> 3) & 1) * 16;
                uint32_t bw[2][4];
                {
                    uint32_t ob = (wrow + 0 * 16) * 128 + kb + wkof;
                    LDSM4(bw[0], wB + (ob ^ ((ob >> 3) & 0x70)));
                }
#pragma unroll
                for (int p = 0; p < NILIM / 2; ++p) {
                    int cur = p & 1;
                    if (p + 1 < NILIM / 2) {
                        uint32_t ob = (wrow + (p + 1) * 16) * 128 + kb + wkof;
                        LDSM4(bw[cur ^ 1], wB + (ob ^ ((ob >> 3) & 0x70)));
                    }
#pragma unroll
                    for (int mi = 0; mi < 4; ++mi)
                        MMA_F16(acc[mi][2 * p], af[mi], bw[cur][0], bw[cur][1]);
#pragma unroll
                    for (int mi = 0; mi < 4; ++mi)
                        MMA_F16(acc[mi][2 * p + 1], af[mi], bw[cur][2], bw[cur][3]);
                }
            }
        }
        if (s + 2 < NSTG) load_stage(s + 2, (s + 2) % 3);
        else CP_COMMIT();   // keep group counts consistent for CP_WAIT(1)
    }
}

// ---------------------------------------------------------------------------
// Single-product fp16 HMMA GEMM with fused reduction epilogue (round-9
// version, verbatim: m-major g_part, coalesced-ish epilogue stores).
// ---------------------------------------------------------------------------
__global__ __launch_bounds__(128, 2)
void gemm_kernel() {
    extern __shared__ char smc[];
    const uint32_t sb = smem_u32(smc);
    const int tid  = threadIdx.x;
    const int wid  = tid >> 5;
    const int lane = tid & 31;
    const int wm   = wid & 1;
    const int wn   = wid >> 1;
    const int nt   = blockIdx.x;
    const int n0   = nt * BN;
    const int m0   = blockIdx.y * BM;

    float* sWg0  = (float*)(smc + SMO_RW);
    float* sWg1  = sWg0 + BN;
    float* sWd   = sWg1 + BN;
    float* sBias = sWd + BN;
    for (int i = tid; i < BN; i += 128) {
        sWg0[i]  = g_rw[0 * NP + n0 + i];
        sWg1[i]  = g_rw[1 * NP + n0 + i];
        sWd[i]   = g_rw[2 * NP + n0 + i];
        sBias[i] = g_rw[3 * NP + n0 + i];
    }

    float acc[4][8][4];
#pragma unroll
    for (int a = 0; a < 4; ++a)
#pragma unroll
        for (int b = 0; b < 8; ++b)
#pragma unroll
            for (int c = 0; c < 4; ++c) acc[a][b][c] = 0.f;

    if (nt != NT - 1)      run_mainloop<8>(acc, sb, m0, n0, tid, lane, wm, wn);
    else if (wn == 0)      run_mainloop<6>(acc, sb, m0, n0, tid, lane, wm, wn);
    else                   run_mainloop<0>(acc, sb, m0, n0, tid, lane, wm, wn);

    float rs[4][2][3];
#pragma unroll
    for (int mi = 0; mi < 4; ++mi)
#pragma unroll
        for (int e2 = 0; e2 < 2; ++e2)
            rs[mi][e2][0] = rs[mi][e2][1] = rs[mi][e2][2] = 0.f;

#pragma unroll
    for (int mi = 0; mi < 4; ++mi)
#pragma unroll
        for (int ni = 0; ni < 8; ++ni)
#pragma unroll
            for (int e = 0; e < 4; ++e) {
                int col = wn * 64 + ni * 8 + 2 * (lane & 3) + (e & 1);
                float v = fmaxf(acc[mi][ni][e] + sBias[col], 0.f);
                rs[mi][e >> 1][0] = fmaf(v, sWg0[col], rs[mi][e >> 1][0]);
                rs[mi][e >> 1][1] = fmaf(v, sWg1[col], rs[mi][e >> 1][1]);
                rs[mi][e >> 1][2] = fmaf(v, sWd[col],  rs[mi][e >> 1][2]);
            }

    const int slot = nt * 2 + wn;
#pragma unroll
    for (int mi = 0; mi < 4; ++mi)
#pragma unroll
        for (int e2 = 0; e2 < 2; ++e2)
#pragma unroll
            for (int ch = 0; ch < 3; ++ch) {
                float v = rs[mi][e2][ch];
                v += __shfl_xor_sync(0xffffffffu, v, 1);
                v += __shfl_xor_sync(0xffffffffu, v, 2);
                if ((lane & 3) == 0) {
                    int row = m0 + wm * 64 + mi * 16 + (lane >> 2) + e2 * 8;
                    g_part[((size_t)ch * NSLOT + slot) * Msz + row] = v;
                }
            }
}

// ---------------------------------------------------------------------------
// finalize: combine partials -> gate, gate_next, distances.
// ---------------------------------------------------------------------------
__global__ void finalize_kernel(const float* __restrict__ gate2_b,
                                const float* __restrict__ dist_b,
                                float* __restrict__ out) {
    int m = blockIdx.x * blockDim.x + threadIdx.x;
    if (m >= Msz) return;
    float s0 = 0.f, s1 = 0.f, sd = 0.f;
#pragma unroll
    for (int sl = 0; sl < NSLOT; ++sl) {
        s0 += g_part[(0 * NSLOT + sl) * (size_t)Msz + m];
        s1 += g_part[(1 * NSLOT + sl) * (size_t)Msz + m];
        sd += g_part[(2 * NSLOT + sl) * (size_t)Msz + m];
    }
    int t = m >> 6, b = m & 63;
    int bt = b * T_ + t;
    float gate  = sigmf(s0 + gate2_b[0]);
    float gaten = sigmf(s1 + gate2_b[1]);
    g_gate[bt]  = gate;
    g_gaten[bt] = gaten;
    out[OFF_GATE + bt] = gate;
    out[OFF_DIST + bt] = sd + dist_b[0];
}

// ---------------------------------------------------------------------------
// mg / mgn cumprod + cum[:, -15:] tail (round-14 phase-split version).
// ---------------------------------------------------------------------------
__global__ void mg_cum_kernel(const float* __restrict__ cum_gate, float* __restrict__ out) {
    int idx = blockIdx.x * blockDim.x + threadIdx.x;
    if (idx >= B_ * T_) return;
    int b = idx >> 10, t = idx & (T_ - 1);
    float g  = g_gate[idx];
    float gn = g_gaten[idx];

    // Phase 1: gather gate_hat and compute independent sigmoids.
    float sm[NSLOTS], sn[NSLOTS];
#pragma unroll
    for (int j = 0; j < NSLOTS; ++j) {
        int s = NSLOTS - j + t;
        float gh = (s < NSLOTS) ? cum_gate[b * NSLOTS + s] : g_gate[b * T_ + (s - NSLOTS)];
        sm[j] = sigmf((g  - gh) * 100.f + 5.f);
        sn[j] = sigmf((gn - gh) * 100.f + 5.f);
    }

    // Phase 2: two independent cumprod chains + stores.
    float pm = 1.f, pn = 1.f;
    float* om = out + OFF_MG  + (size_t)idx * NSLOTS;
    float* on = out + OFF_MGN + (size_t)idx * NSLOTS;
#pragma unroll
    for (int j = 0; j < NSLOTS; ++j) {
        pm *= sm[j];
        pn *= sn[j];
        om[j] = pm;
        on[j] = pn;
    }

    if (idx < B_ * NSLOTS) {
        int bb = idx / NSLOTS, j = idx % NSLOTS;
        out[OFF_CUM + idx] = g_gate[bb * T_ + (T_ - NSLOTS) + j];
    }
}

extern "C" void kernel_launch(void* const* d_in, const int* in_sizes, int n_in,
                              void* d_out, int out_size) {
    const float* emb      = (const float*)d_in[0];
    const float* emb_last = (const float*)d_in[1];
    const float* cum_gate = (const float*)d_in[2];
    const float* conv1_w  = (const float*)d_in[3];
    const float* conv1_b  = (const float*)d_in[4];
    const float* bn_gamma = (const float*)d_in[5];
    const float* bn_beta  = (const float*)d_in[6];
    const float* bn_mean  = (const float*)d_in[7];
    const float* bn_var   = (const float*)d_in[8];
    const float* gate2_w  = (const float*)d_in[9];
    const float* gate2_b  = (const float*)d_in[10];
    const float* dist_w   = (const float*)d_in[11];
    const float* dist_b   = (const float*)d_in[12];
    float* out = (float*)d_out;

    cudaFuncSetAttribute(gemm_kernel, cudaFuncAttributeMaxDynamicSharedMemorySize,
                         SMEM_TOTAL);

    prep_kernel<<<PREP_BLOCKS, 256>>>(emb, emb_last, conv1_w, conv1_b, bn_gamma,
                                      bn_beta, bn_mean, bn_var, gate2_w, dist_w, out);
    gemm_kernel<<<dim3(NT, MT), 128, SMEM_TOTAL>>>();
    finalize_kernel<<<Msz / 256, 256>>>(gate2_b, dist_b, out);
    mg_cum_kernel<<<(B_ * T_) / 256, 256>>>(cum_gate, out);
}

// round 16
// speedup vs baseline: 1.0172x; 1.0034x over previous
#include <cuda_runtime.h>
#include <cuda_fp16.h>
#include <math.h>
#include <stdint.h>

// ---------------------------------------------------------------------------
// Problem constants
// ---------------------------------------------------------------------------
constexpr int T_     = 1024;
constexpr int B_     = 64;
constexpr int NINP   = 800;
constexpr int NHID   = 1200;
constexpr int NSLOTS = 15;

constexpr int Msz   = T_ * B_;     // 65536 rows (m = t*64 + b)
constexpr int Ksz   = 2 * NINP;    // 1600
constexpr int NP    = 1280;        // NHID padded
constexpr int Erows = Msz + B_;    // 65600 rows of emb_full flattened [t][b]

constexpr int BM = 128, BN = 128, BK = 64;
constexpr int NSTG  = Ksz / BK;    // 25
constexpr int NT    = NP / BN;     // 10
constexpr int MT    = Msz / BM;    // 512
constexpr int NSLOT = NT * 2;      // 20 partial slots

// Output layout
constexpr size_t OFF_MG   = 0;
constexpr size_t OFF_MGN  = (size_t)B_ * T_ * NSLOTS;
constexpr size_t OFF_GATE = OFF_MGN + (size_t)B_ * T_ * NSLOTS;
constexpr size_t OFF_DIST = OFF_GATE + (size_t)B_ * T_;
constexpr size_t OFF_EMB  = OFF_DIST + (size_t)B_ * T_;
constexpr size_t OFF_CUM  = OFF_EMB + (size_t)B_ * NINP;

// Scratch (device globals)
__device__ __half g_E[(size_t)Erows * NINP];    // 105 MB  fp16 emb_full
__device__ __half g_W[(size_t)NP * Ksz];        // 4.1 MB  [n][k], BN folded, fp16
__device__ float g_rw[4 * NP];                  // wg0, wg1, wd, bias
__device__ float g_part[3 * NSLOT * Msz];       // epilogue partials, m-major
__device__ float g_gate[(size_t)B_ * T_];
__device__ float g_gaten[(size_t)B_ * T_];

// Fast sigmoid: 1/(1+2^(-x*log2e)) via ex2.approx + rcp.approx (2 MUFU ops).
__device__ __forceinline__ float sigmf(float x) {
    float e, r;
    asm("ex2.approx.f32 %0, %1;" : "=f"(e) : "f"(-x * 1.4426950408889634f));
    asm("rcp.approx.f32 %0, %1;" : "=f"(r) : "f"(1.0f + e));
    return r;
}

// ---------------------------------------------------------------------------
// PTX helpers (base sm_103 target: cp.async / ldmatrix / mma.sync)
// ---------------------------------------------------------------------------
__device__ __forceinline__ uint32_t smem_u32(const void* p) {
    uint32_t a;
    asm("{ .reg .u64 t; cvta.to.shared.u64 t, %1; cvt.u32.u64 %0, t; }" : "=r"(a) : "l"(p));
    return a;
}
__device__ __forceinline__ void cpasync16(uint32_t dst, const void* src) {
    asm volatile("cp.async.cg.shared.global [%0], [%1], 16;" :: "r"(dst), "l"(src));
}
#define CP_COMMIT() asm volatile("cp.async.commit_group;" ::: "memory")
#define CP_WAIT(N)  asm volatile("cp.async.wait_group %0;" :: "n"(N) : "memory")

#define LDSM4(r, addr)                                                          \
    asm volatile("ldmatrix.sync.aligned.m8n8.x4.shared.b16 {%0,%1,%2,%3}, [%4];" \
        : "=r"((r)[0]), "=r"((r)[1]), "=r"((r)[2]), "=r"((r)[3]) : "r"(addr))

#define MMA_F16(c, a, b0, b1)                                                   \
    asm volatile("mma.sync.aligned.m16n8k16.row.col.f32.f16.f16.f32 "           \
        "{%0,%1,%2,%3}, {%4,%5,%6,%7}, {%8,%9}, {%0,%1,%2,%3};"                 \
        : "+f"((c)[0]), "+f"((c)[1]), "+f"((c)[2]), "+f"((c)[3])                \
        : "r"((a)[0]), "r"((a)[1]), "r"((a)[2]), "r"((a)[3]),                   \
          "r"(b0), "r"(b1))

// SMEM layout (dynamic):
//   [0, 2048)        : wg0/wg1/wd/bias (4 x 128 floats)
//   [4096, +3*32768) : 3 stages of [A 16K][W 16K]
constexpr int SMO_RW  = 0;
constexpr int SMO_STG = 4096;
constexpr int SZ_A  = BM * 128;              // 16384 (128 rows x 128B)
constexpr int SZ_W  = BN * 128;              // 16384
constexpr int STAGE_SZ = SZ_A + SZ_W;        // 32768
constexpr int SMEM_TOTAL = SMO_STG + 3 * STAGE_SZ;  // 102400 (x2 CTAs <= 228KB)

// prep_kernel block partition. pack_e: each thread handles FOUR group-chunks
// (one from each quarter of the group space) -> 4 independent LDG.128.
constexpr int PE_GROUPS = Erows * (NINP / 4);                // 13,120,000
constexpr int PE_QUART  = PE_GROUPS / 4;                     // 3,280,000
constexpr int PE_BLOCKS = (PE_QUART + 255) / 256;            // 12813
constexpr int PW_BLOCKS = (NP * (Ksz / 2) + 255) / 256;      // 4000
constexpr int TE_BLOCKS = (B_ * NINP + 255) / 256;           // 200
constexpr int PREP_BLOCKS = PE_BLOCKS + PW_BLOCKS + TE_BLOCKS;

// ---------------------------------------------------------------------------
// prep: merged pack_e (4 chunks/thread, MLP=4) + pack_w + tail_emb.
// ---------------------------------------------------------------------------
__global__ void prep_kernel(const float* __restrict__ emb,
                            const float* __restrict__ emb_last,
                            const float* __restrict__ conv1_w,
                            const float* __restrict__ conv1_b,
                            const float* __restrict__ gamma,
                            const float* __restrict__ beta,
                            const float* __restrict__ mean,
                            const float* __restrict__ var,
                            const float* __restrict__ gate2_w,
                            const float* __restrict__ dist_w,
                            float* __restrict__ out) {
    const int bx = blockIdx.x;
    if (bx < PE_BLOCKS) {
        // ---- pack_e: emb_full -> fp16. Four group-chunks per thread, one in
        // each quarter of the group space (all quarters warp-coalesced). All
        // 4 LDG.128 issued before any convert/store -> MLP=4.
        int i0 = bx * 256 + threadIdx.x;
        if (i0 >= PE_QUART) return;
        float4 v[4];
        int gi[4];
#pragma unroll
        for (int c = 0; c < 4; ++c) {
            int g = i0 + c * PE_QUART;
            gi[c] = g;
            int r = g / (NINP / 4);
            int k = (g - r * (NINP / 4)) * 4;
            const float* src = (r < B_) ? (emb_last + (size_t)r * NINP + k)
                                        : (emb + (size_t)(r - B_) * NINP + k);
            v[c] = *(const float4*)src;
        }
#pragma unroll
        for (int c = 0; c < 4; ++c) {
            __half2 h0; h0.x = __float2half_rn(v[c].x); h0.y = __float2half_rn(v[c].y);
            __half2 h1; h1.x = __float2half_rn(v[c].z); h1.y = __float2half_rn(v[c].w);
            uint2 pk; pk.x = *(uint32_t*)&h0; pk.y = *(uint32_t*)&h1;
            *(reinterpret_cast<uint2*>(g_E) + gi[c]) = pk;
        }
    } else if (bx < PE_BLOCKS + PW_BLOCKS) {
        // ---- pack_w: BN-folded fp16 weights + reduction vectors ----
        int idx = (bx - PE_BLOCKS) * 256 + threadIdx.x;   // pair index
        if (idx >= NP * (Ksz / 2)) return;
        int n = idx / (Ksz / 2);
        int k = (idx - n * (Ksz / 2)) * 2;
        float w0 = 0.f, w1 = 0.f;
        if (n < NHID) {
            float scale = gamma[n] * rsqrtf(var[n] + 1e-5f);
            int c = (k < NINP) ? 0 : 1;
            int i = (k < NINP) ? k : k - NINP;
            w0 = conv1_w[(size_t)n * Ksz + i * 2 + c] * scale;
            w1 = conv1_w[(size_t)n * Ksz + (i + 1) * 2 + c] * scale;
        }
        __half2 pw; pw.x = __float2half_rn(w0); pw.y = __float2half_rn(w1);
        reinterpret_cast<__half2*>(g_W)[idx] = pw;

        if (idx < NP) {
            int h = idx;
            float wg0 = 0.f, wg1 = 0.f, wd = 0.f, bz = 0.f;
            if (h < NHID) {
                if (h < 600) wg0 = gate2_w[h]; else wg1 = gate2_w[h];
                wd = dist_w[h];
                float scale = gamma[h] * rsqrtf(var[h] + 1e-5f);
                bz = (conv1_b[h] - mean[h]) * scale + beta[h];
            }
            g_rw[0 * NP + h] = wg0;
            g_rw[1 * NP + h] = wg1;
            g_rw[2 * NP + h] = wd;
            g_rw[3 * NP + h] = bz;
        }
    } else {
        // ---- tail_emb: emb_full[-1] copy ----
        int i = (bx - PE_BLOCKS - PW_BLOCKS) * 256 + threadIdx.x;
        if (i < B_ * NINP)
            out[OFF_EMB + i] = emb[(size_t)(T_ - 1) * B_ * NINP + i];
    }
}

// ---------------------------------------------------------------------------
// Templated mainloop (round-9 version, verbatim).
// NILIM compile-time: 8 (full), 6 (last tile wn=0), 0 (last tile wn=1).
// ---------------------------------------------------------------------------
template<int NILIM>
__device__ __forceinline__ void run_mainloop(
    float (&acc)[4][8][4], uint32_t sb, int m0, int n0,
    int tid, int lane, int wm, int wn) {

    auto load_stage = [&](int s, int buf) {
        const int k0 = s * BK;
        const uint32_t base = sb + SMO_STG + buf * STAGE_SZ;
#pragma unroll
        for (int i = 0; i < 16; ++i) {
            int q = tid + i * 128;
            const __half* src;
            uint32_t off;
            if (q < 1024) {                       // A: 128 rows x 8 16B-chunks
                int rr  = q >> 3;
                int cb  = q & 7;
                int k   = k0 + cb * 8;
                int row = m0 + rr + ((k < NINP) ? 0 : B_);
                int kk  = (k < NINP) ? k : (k - NINP);
                src = g_E + (size_t)row * NINP + kk;
                uint32_t o = rr * 128 + cb * 16;
                off = o ^ ((o >> 3) & 0x70);
            } else {                              // W: 128 rows x 8 chunks
                int w   = q - 1024;
                int rr  = w >> 3;
                int cb  = w & 7;
                src = g_W + (size_t)(n0 + rr) * Ksz + k0 + cb * 8;
                uint32_t o = rr * 128 + cb * 16;
                off = SZ_A + (o ^ ((o >> 3) & 0x70));
            }
            cpasync16(base + off, src);
        }
        CP_COMMIT();
    };

    load_stage(0, 0);
    load_stage(1, 1);

    for (int s = 0; s < NSTG; ++s) {
        const int buf = (s < 3) ? s : (s % 3);
        CP_WAIT(1);
        __syncthreads();   // stage s resident; all warps past stage s-1

        if (NILIM > 0) {
            const uint32_t aB = sb + SMO_STG + buf * STAGE_SZ;
            const uint32_t wB = aB + SZ_A;
#pragma unroll
            for (int kt = 0; kt < 4; ++kt) {
                const int kb = kt * 32;
                uint32_t af[4][4];
#pragma unroll
                for (int mi = 0; mi < 4; ++mi) {
                    int row = wm * 64 + mi * 16 + (lane & 15);
                    uint32_t o  = row * 128 + kb + ((lane >> 4) * 16);
                    uint32_t so = o ^ ((o >> 3) & 0x70);
                    LDSM4(af[mi], aB + so);
                }
                const int wrow = wn * 64 + ((lane >> 4) * 8) + (lane & 7);
                const int wkof = ((lane >> 3) & 1) * 16;
                uint32_t bw[2][4];
                {
                    uint32_t ob = (wrow + 0 * 16) * 128 + kb + wkof;
                    LDSM4(bw[0], wB + (ob ^ ((ob >> 3) & 0x70)));
                }
#pragma unroll
                for (int p = 0; p < NILIM / 2; ++p) {
                    int cur = p & 1;
                    if (p + 1 < NILIM / 2) {
                        uint32_t ob = (wrow + (p + 1) * 16) * 128 + kb + wkof;
                        LDSM4(bw[cur ^ 1], wB + (ob ^ ((ob >> 3) & 0x70)));
                    }
#pragma unroll
                    for (int mi = 0; mi < 4; ++mi)
                        MMA_F16(acc[mi][2 * p], af[mi], bw[cur][0], bw[cur][1]);
#pragma unroll
                    for (int mi = 0; mi < 4; ++mi)
                        MMA_F16(acc[mi][2 * p + 1], af[mi], bw[cur][2], bw[cur][3]);
                }
            }
        }
        if (s + 2 < NSTG) load_stage(s + 2, (s + 2) % 3);
        else CP_COMMIT();   // keep group counts consistent for CP_WAIT(1)
    }
}

// ---------------------------------------------------------------------------
// Single-product fp16 HMMA GEMM with fused reduction epilogue (round-9
// version, verbatim: m-major g_part, coalesced-ish epilogue stores).
// ---------------------------------------------------------------------------
__global__ __launch_bounds__(128, 2)
void gemm_kernel() {
    extern __shared__ char smc[];
    const uint32_t sb = smem_u32(smc);
    const int tid  = threadIdx.x;
    const int wid  = tid >> 5;
    const int lane = tid & 31;
    const int wm   = wid & 1;
    const int wn   = wid >> 1;
    const int nt   = blockIdx.x;
    const int n0   = nt * BN;
    const int m0   = blockIdx.y * BM;

    float* sWg0  = (float*)(smc + SMO_RW);
    float* sWg1  = sWg0 + BN;
    float* sWd   = sWg1 + BN;
    float* sBias = sWd + BN;
    for (int i = tid; i < BN; i += 128) {
        sWg0[i]  = g_rw[0 * NP + n0 + i];
        sWg1[i]  = g_rw[1 * NP + n0 + i];
        sWd[i]   = g_rw[2 * NP + n0 + i];
        sBias[i] = g_rw[3 * NP + n0 + i];
    }

    float acc[4][8][4];
#pragma unroll
    for (int a = 0; a < 4; ++a)
#pragma unroll
        for (int b = 0; b < 8; ++b)
#pragma unroll
            for (int c = 0; c < 4; ++c) acc[a][b][c] = 0.f;

    if (nt != NT - 1)      run_mainloop<8>(acc, sb, m0, n0, tid, lane, wm, wn);
    else if (wn == 0)      run_mainloop<6>(acc, sb, m0, n0, tid, lane, wm, wn);
    else                   run_mainloop<0>(acc, sb, m0, n0, tid, lane, wm, wn);

    float rs[4][2][3];
#pragma unroll
    for (int mi = 0; mi < 4; ++mi)
#pragma unroll
        for (int e2 = 0; e2 < 2; ++e2)
            rs[mi][e2][0] = rs[mi][e2][1] = rs[mi][e2][2] = 0.f;

#pragma unroll
    for (int mi = 0; mi < 4; ++mi)
#pragma unroll
        for (int ni = 0; ni < 8; ++ni)
#pragma unroll
            for (int e = 0; e < 4; ++e) {
                int col = wn * 64 + ni * 8 + 2 * (lane & 3) + (e & 1);
                float v = fmaxf(acc[mi][ni][e] + sBias[col], 0.f);
                rs[mi][e >> 1][0] = fmaf(v, sWg0[col], rs[mi][e >> 1][0]);
                rs[mi][e >> 1][1] = fmaf(v, sWg1[col], rs[mi][e >> 1][1]);
                rs[mi][e >> 1][2] = fmaf(v, sWd[col],  rs[mi][e >> 1][2]);
            }

    const int slot = nt * 2 + wn;
#pragma unroll
    for (int mi = 0; mi < 4; ++mi)
#pragma unroll
        for (int e2 = 0; e2 < 2; ++e2)
#pragma unroll
            for (int ch = 0; ch < 3; ++ch) {
                float v = rs[mi][e2][ch];
                v += __shfl_xor_sync(0xffffffffu, v, 1);
                v += __shfl_xor_sync(0xffffffffu, v, 2);
                if ((lane & 3) == 0) {
                    int row = m0 + wm * 64 + mi * 16 + (lane >> 2) + e2 * 8;
                    g_part[((size_t)ch * NSLOT + slot) * Msz + row] = v;
                }
            }
}

// ---------------------------------------------------------------------------
// finalize: combine partials -> gate, gate_next, distances.
// ---------------------------------------------------------------------------
__global__ void finalize_kernel(const float* __restrict__ gate2_b,
                                const float* __restrict__ dist_b,
                                float* __restrict__ out) {
    int m = blockIdx.x * blockDim.x + threadIdx.x;
    if (m >= Msz) return;
    float s0 = 0.f, s1 = 0.f, sd = 0.f;
#pragma unroll
    for (int sl = 0; sl < NSLOT; ++sl) {
        s0 += g_part[(0 * NSLOT + sl) * (size_t)Msz + m];
        s1 += g_part[(1 * NSLOT + sl) * (size_t)Msz + m];
        sd += g_part[(2 * NSLOT + sl) * (size_t)Msz + m];
    }
    int t = m >> 6, b = m & 63;
    int bt = b * T_ + t;
    float gate  = sigmf(s0 + gate2_b[0]);
    float gaten = sigmf(s1 + gate2_b[1]);
    g_gate[bt]  = gate;
    g_gaten[bt] = gaten;
    out[OFF_GATE + bt] = gate;
    out[OFF_DIST + bt] = sd + dist_b[0];
}

// ---------------------------------------------------------------------------
// mg / mgn cumprod + cum[:, -15:] tail. Channel-split: thread handles ONE of
// {mg, mgn} for one (b,t) -> 2x threads, half the latency chain per thread.
// Same float ops per output in the same order => bit-identical results.
// ---------------------------------------------------------------------------
__global__ void mg_cum_kernel(const float* __restrict__ cum_gate, float* __restrict__ out) {
    int idx = blockIdx.x * blockDim.x + threadIdx.x;
    if (idx >= 2 * B_ * T_) return;
    int ch  = idx >> 16;               // 0 = mg, 1 = mgn
    int bt  = idx & (B_ * T_ - 1);
    int b = bt >> 10, t = bt & (T_ - 1);
    float gv = ch ? g_gaten[bt] : g_gate[bt];

    // Phase 1: gather gate_hat and compute independent sigmoids.
    float sv[NSLOTS];
#pragma unroll
    for (int j = 0; j < NSLOTS; ++j) {
        int s = NSLOTS - j + t;
        float gh = (s < NSLOTS) ? cum_gate[b * NSLOTS + s] : g_gate[b * T_ + (s - NSLOTS)];
        sv[j] = sigmf((gv - gh) * 100.f + 5.f);
    }

    // Phase 2: cumprod chain + stores.
    float p = 1.f;
    float* o = out + (ch ? OFF_MGN : OFF_MG) + (size_t)bt * NSLOTS;
#pragma unroll
    for (int j = 0; j < NSLOTS; ++j) {
        p *= sv[j];
        o[j] = p;
    }

    // cum[:, -15:] tail (from the ch==0 range only)
    if (idx < B_ * NSLOTS) {
        int bb = idx / NSLOTS, j = idx % NSLOTS;
        out[OFF_CUM + idx] = g_gate[bb * T_ + (T_ - NSLOTS) + j];
    }
}

extern "C" void kernel_launch(void* const* d_in, const int* in_sizes, int n_in,
                              void* d_out, int out_size) {
    const float* emb      = (const float*)d_in[0];
    const float* emb_last = (const float*)d_in[1];
    const float* cum_gate = (const float*)d_in[2];
    const float* conv1_w  = (const float*)d_in[3];
    const float* conv1_b  = (const float*)d_in[4];
    const float* bn_gamma = (const float*)d_in[5];
    const float* bn_beta  = (const float*)d_in[6];
    const float* bn_mean  = (const float*)d_in[7];
    const float* bn_var   = (const float*)d_in[8];
    const float* gate2_w  = (const float*)d_in[9];
    const float* gate2_b  = (const float*)d_in[10];
    const float* dist_w   = (const float*)d_in[11];
    const float* dist_b   = (const float*)d_in[12];
    float* out = (float*)d_out;

    cudaFuncSetAttribute(gemm_kernel, cudaFuncAttributeMaxDynamicSharedMemorySize,
                         SMEM_TOTAL);

    prep_kernel<<<PREP_BLOCKS, 256>>>(emb, emb_last, conv1_w, conv1_b, bn_gamma,
                                      bn_beta, bn_mean, bn_var, gate2_w, dist_w, out);
    gemm_kernel<<<dim3(NT, MT), 128, SMEM_TOTAL>>>();
    finalize_kernel<<<Msz / 256, 256>>>(gate2_b, dist_b, out);
    mg_cum_kernel<<<(2 * B_ * T_) / 256, 256>>>(cum_gate, out);
}

// round 17
// speedup vs baseline: 1.0305x; 1.0131x over previous
#include <cuda_runtime.h>
#include <cuda_fp16.h>
#include <math.h>
#include <stdint.h>

// ---------------------------------------------------------------------------
// Problem constants
// ---------------------------------------------------------------------------
constexpr int T_     = 1024;
constexpr int B_     = 64;
constexpr int NINP   = 800;
constexpr int NHID   = 1200;
constexpr int NSLOTS = 15;

constexpr int Msz   = T_ * B_;     // 65536 rows (m = t*64 + b)
constexpr int Ksz   = 2 * NINP;    // 1600
constexpr int NP    = 1280;        // NHID padded
constexpr int Erows = Msz + B_;    // 65600 rows of emb_full flattened [t][b]

constexpr int BM = 128, BN = 128, BK = 64;
constexpr int NSTG  = Ksz / BK;    // 25
constexpr int NT    = NP / BN;     // 10
constexpr int MT    = Msz / BM;    // 512
constexpr int NSLOT = NT * 2;      // 20 partial slots

// Output layout
constexpr size_t OFF_MG   = 0;
constexpr size_t OFF_MGN  = (size_t)B_ * T_ * NSLOTS;
constexpr size_t OFF_GATE = OFF_MGN + (size_t)B_ * T_ * NSLOTS;
constexpr size_t OFF_DIST = OFF_GATE + (size_t)B_ * T_;
constexpr size_t OFF_EMB  = OFF_DIST + (size_t)B_ * T_;
constexpr size_t OFF_CUM  = OFF_EMB + (size_t)B_ * NINP;

// Scratch (device globals)
__device__ __half g_E[(size_t)Erows * NINP];    // 105 MB  fp16 emb_full
__device__ __half g_W[(size_t)NP * Ksz];        // 4.1 MB  [n][k], BN folded, fp16
__device__ float g_rw[4 * NP];                  // wg0, wg1, wd, bias
__device__ float g_part[3 * NSLOT * Msz];       // epilogue partials, m-major
__device__ float g_gate[(size_t)B_ * T_];
__device__ float g_gaten[(size_t)B_ * T_];

// Fast sigmoid: 1/(1+2^(-x*log2e)) via ex2.approx + rcp.approx (2 MUFU ops).
__device__ __forceinline__ float sigmf(float x) {
    float e, r;
    asm("ex2.approx.f32 %0, %1;" : "=f"(e) : "f"(-x * 1.4426950408889634f));
    asm("rcp.approx.f32 %0, %1;" : "=f"(r) : "f"(1.0f + e));
    return r;
}

// ---------------------------------------------------------------------------
// PTX helpers (base sm_103 target: cp.async / ldmatrix / mma.sync)
// ---------------------------------------------------------------------------
__device__ __forceinline__ uint32_t smem_u32(const void* p) {
    uint32_t a;
    asm("{ .reg .u64 t; cvta.to.shared.u64 t, %1; cvt.u32.u64 %0, t; }" : "=r"(a) : "l"(p));
    return a;
}
__device__ __forceinline__ void cpasync16(uint32_t dst, const void* src) {
    asm volatile("cp.async.cg.shared.global [%0], [%1], 16;" :: "r"(dst), "l"(src));
}
#define CP_COMMIT() asm volatile("cp.async.commit_group;" ::: "memory")
#define CP_WAIT(N)  asm volatile("cp.async.wait_group %0;" :: "n"(N) : "memory")

#define LDSM4(r, addr)                                                          \
    asm volatile("ldmatrix.sync.aligned.m8n8.x4.shared.b16 {%0,%1,%2,%3}, [%4];" \
        : "=r"((r)[0]), "=r"((r)[1]), "=r"((r)[2]), "=r"((r)[3]) : "r"(addr))

#define MMA_F16(c, a, b0, b1)                                                   \
    asm volatile("mma.sync.aligned.m16n8k16.row.col.f32.f16.f16.f32 "           \
        "{%0,%1,%2,%3}, {%4,%5,%6,%7}, {%8,%9}, {%0,%1,%2,%3};"                 \
        : "+f"((c)[0]), "+f"((c)[1]), "+f"((c)[2]), "+f"((c)[3])                \
        : "r"((a)[0]), "r"((a)[1]), "r"((a)[2]), "r"((a)[3]),                   \
          "r"(b0), "r"(b1))

// SMEM layout (dynamic):
//   [0, 2048)        : wg0/wg1/wd/bias (4 x 128 floats)
//   [4096, +3*32768) : 3 stages of [A 16K][W 16K]
constexpr int SMO_RW  = 0;
constexpr int SMO_STG = 4096;
constexpr int SZ_A  = BM * 128;              // 16384 (128 rows x 128B)
constexpr int SZ_W  = BN * 128;              // 16384
constexpr int STAGE_SZ = SZ_A + SZ_W;        // 32768
constexpr int SMEM_TOTAL = SMO_STG + 3 * STAGE_SZ;  // 102400 (x2 CTAs <= 228KB)

// prep_kernel block partition. pack_e: each thread handles FOUR group-chunks
// (one from each quarter of the group space) -> 4 independent LDG.128.
constexpr int PE_GROUPS = Erows * (NINP / 4);                // 13,120,000
constexpr int PE_QUART  = PE_GROUPS / 4;                     // 3,280,000
constexpr int PE_BLOCKS = (PE_QUART + 255) / 256;            // 12813
constexpr int PW_BLOCKS = (NP * (Ksz / 2) + 255) / 256;      // 4000
constexpr int TE_BLOCKS = (B_ * NINP + 255) / 256;           // 200
constexpr int PREP_BLOCKS = PE_BLOCKS + PW_BLOCKS + TE_BLOCKS;

// ---------------------------------------------------------------------------
// prep: merged pack_e (4 chunks/thread, MLP=4) + pack_w + tail_emb.
// (round-16 version, unchanged)
// ---------------------------------------------------------------------------
__global__ void prep_kernel(const float* __restrict__ emb,
                            const float* __restrict__ emb_last,
                            const float* __restrict__ conv1_w,
                            const float* __restrict__ conv1_b,
                            const float* __restrict__ gamma,
                            const float* __restrict__ beta,
                            const float* __restrict__ mean,
                            const float* __restrict__ var,
                            const float* __restrict__ gate2_w,
                            const float* __restrict__ dist_w,
                            float* __restrict__ out) {
    const int bx = blockIdx.x;
    if (bx < PE_BLOCKS) {
        int i0 = bx * 256 + threadIdx.x;
        if (i0 >= PE_QUART) return;
        float4 v[4];
        int gi[4];
#pragma unroll
        for (int c = 0; c < 4; ++c) {
            int g = i0 + c * PE_QUART;
            gi[c] = g;
            int r = g / (NINP / 4);
            int k = (g - r * (NINP / 4)) * 4;
            const float* src = (r < B_) ? (emb_last + (size_t)r * NINP + k)
                                        : (emb + (size_t)(r - B_) * NINP + k);
            v[c] = *(const float4*)src;
        }
#pragma unroll
        for (int c = 0; c < 4; ++c) {
            __half2 h0; h0.x = __float2half_rn(v[c].x); h0.y = __float2half_rn(v[c].y);
            __half2 h1; h1.x = __float2half_rn(v[c].z); h1.y = __float2half_rn(v[c].w);
            uint2 pk; pk.x = *(uint32_t*)&h0; pk.y = *(uint32_t*)&h1;
            *(reinterpret_cast<uint2*>(g_E) + gi[c]) = pk;
        }
    } else if (bx < PE_BLOCKS + PW_BLOCKS) {
        int idx = (bx - PE_BLOCKS) * 256 + threadIdx.x;   // pair index
        if (idx >= NP * (Ksz / 2)) return;
        int n = idx / (Ksz / 2);
        int k = (idx - n * (Ksz / 2)) * 2;
        float w0 = 0.f, w1 = 0.f;
        if (n < NHID) {
            float scale = gamma[n] * rsqrtf(var[n] + 1e-5f);
            int c = (k < NINP) ? 0 : 1;
            int i = (k < NINP) ? k : k - NINP;
            w0 = conv1_w[(size_t)n * Ksz + i * 2 + c] * scale;
            w1 = conv1_w[(size_t)n * Ksz + (i + 1) * 2 + c] * scale;
        }
        __half2 pw; pw.x = __float2half_rn(w0); pw.y = __float2half_rn(w1);
        reinterpret_cast<__half2*>(g_W)[idx] = pw;

        if (idx < NP) {
            int h = idx;
            float wg0 = 0.f, wg1 = 0.f, wd = 0.f, bz = 0.f;
            if (h < NHID) {
                if (h < 600) wg0 = gate2_w[h]; else wg1 = gate2_w[h];
                wd = dist_w[h];
                float scale = gamma[h] * rsqrtf(var[h] + 1e-5f);
                bz = (conv1_b[h] - mean[h]) * scale + beta[h];
            }
            g_rw[0 * NP + h] = wg0;
            g_rw[1 * NP + h] = wg1;
            g_rw[2 * NP + h] = wd;
            g_rw[3 * NP + h] = bz;
        }
    } else {
        int i = (bx - PE_BLOCKS - PW_BLOCKS) * 256 + threadIdx.x;
        if (i < B_ * NINP)
            out[OFF_EMB + i] = emb[(size_t)(T_ - 1) * B_ * NINP + i];
    }
}

// ---------------------------------------------------------------------------
// Templated mainloop (round-9 version, verbatim).
// ---------------------------------------------------------------------------
template<int NILIM>
__device__ __forceinline__ void run_mainloop(
    float (&acc)[4][8][4], uint32_t sb, int m0, int n0,
    int tid, int lane, int wm, int wn) {

    auto load_stage = [&](int s, int buf) {
        const int k0 = s * BK;
        const uint32_t base = sb + SMO_STG + buf * STAGE_SZ;
#pragma unroll
        for (int i = 0; i < 16; ++i) {
            int q = tid + i * 128;
            const __half* src;
            uint32_t off;
            if (q < 1024) {                       // A: 128 rows x 8 16B-chunks
                int rr  = q >> 3;
                int cb  = q & 7;
                int k   = k0 + cb * 8;
                int row = m0 + rr + ((k < NINP) ? 0 : B_);
                int kk  = (k < NINP) ? k : (k - NINP);
                src = g_E + (size_t)row * NINP + kk;
                uint32_t o = rr * 128 + cb * 16;
                off = o ^ ((o >> 3) & 0x70);
            } else {                              // W: 128 rows x 8 chunks
                int w   = q - 1024;
                int rr  = w >> 3;
                int cb  = w & 7;
                src = g_W + (size_t)(n0 + rr) * Ksz + k0 + cb * 8;
                uint32_t o = rr * 128 + cb * 16;
                off = SZ_A + (o ^ ((o >> 3) & 0x70));
            }
            cpasync16(base + off, src);
        }
        CP_COMMIT();
    };

    load_stage(0, 0);
    load_stage(1, 1);

    for (int s = 0; s < NSTG; ++s) {
        const int buf = (s < 3) ? s : (s % 3);
        CP_WAIT(1);
        __syncthreads();   // stage s resident; all warps past stage s-1

        if (NILIM > 0) {
            const uint32_t aB = sb + SMO_STG + buf * STAGE_SZ;
            const uint32_t wB = aB + SZ_A;
#pragma unroll
            for (int kt = 0; kt < 4; ++kt) {
                const int kb = kt * 32;
                uint32_t af[4][4];
#pragma unroll
                for (int mi = 0; mi < 4; ++mi) {
                    int row = wm * 64 + mi * 16 + (lane & 15);
                    uint32_t o  = row * 128 + kb + ((lane >> 4) * 16);
                    uint32_t so = o ^ ((o >> 3) & 0x70);
                    LDSM4(af[mi], aB + so);
                }
                const int wrow = wn * 64 + ((lane >> 4) * 8) + (lane & 7);
                const int wkof = ((lane >> 3) & 1) * 16;
                uint32_t bw[2][4];
                {
                    uint32_t ob = (wrow + 0 * 16) * 128 + kb + wkof;
                    LDSM4(bw[0], wB + (ob ^ ((ob >> 3) & 0x70)));
                }
#pragma unroll
                for (int p = 0; p < NILIM / 2; ++p) {
                    int cur = p & 1;
                    if (p + 1 < NILIM / 2) {
                        uint32_t ob = (wrow + (p + 1) * 16) * 128 + kb + wkof;
                        LDSM4(bw[cur ^ 1], wB + (ob ^ ((ob >> 3) & 0x70)));
                    }
#pragma unroll
                    for (int mi = 0; mi < 4; ++mi)
                        MMA_F16(acc[mi][2 * p], af[mi], bw[cur][0], bw[cur][1]);
#pragma unroll
                    for (int mi = 0; mi < 4; ++mi)
                        MMA_F16(acc[mi][2 * p + 1], af[mi], bw[cur][2], bw[cur][3]);
                }
            }
        }
        if (s + 2 < NSTG) load_stage(s + 2, (s + 2) % 3);
        else CP_COMMIT();   // keep group counts consistent for CP_WAIT(1)
    }
}

// ---------------------------------------------------------------------------
// Single-product fp16 HMMA GEMM with fused reduction epilogue (round-9
// version, verbatim).
// ---------------------------------------------------------------------------
__global__ __launch_bounds__(128, 2)
void gemm_kernel() {
    extern __shared__ char smc[];
    const uint32_t sb = smem_u32(smc);
    const int tid  = threadIdx.x;
    const int wid  = tid >> 5;
    const int lane = tid & 31;
    const int wm   = wid & 1;
    const int wn   = wid >> 1;
    const int nt   = blockIdx.x;
    const int n0   = nt * BN;
    const int m0   = blockIdx.y * BM;

    float* sWg0  = (float*)(smc + SMO_RW);
    float* sWg1  = sWg0 + BN;
    float* sWd   = sWg1 + BN;
    float* sBias = sWd + BN;
    for (int i = tid; i < BN; i += 128) {
        sWg0[i]  = g_rw[0 * NP + n0 + i];
        sWg1[i]  = g_rw[1 * NP + n0 + i];
        sWd[i]   = g_rw[2 * NP + n0 + i];
        sBias[i] = g_rw[3 * NP + n0 + i];
    }

    float acc[4][8][4];
#pragma unroll
    for (int a = 0; a < 4; ++a)
#pragma unroll
        for (int b = 0; b < 8; ++b)
#pragma unroll
            for (int c = 0; c < 4; ++c) acc[a][b][c] = 0.f;

    if (nt != NT - 1)      run_mainloop<8>(acc, sb, m0, n0, tid, lane, wm, wn);
    else if (wn == 0)      run_mainloop<6>(acc, sb, m0, n0, tid, lane, wm, wn);
    else                   run_mainloop<0>(acc, sb, m0, n0, tid, lane, wm, wn);

    float rs[4][2][3];
#pragma unroll
    for (int mi = 0; mi < 4; ++mi)
#pragma unroll
        for (int e2 = 0; e2 < 2; ++e2)
            rs[mi][e2][0] = rs[mi][e2][1] = rs[mi][e2][2] = 0.f;

#pragma unroll
    for (int mi = 0; mi < 4; ++mi)
#pragma unroll
        for (int ni = 0; ni < 8; ++ni)
#pragma unroll
            for (int e = 0; e < 4; ++e) {
                int col = wn * 64 + ni * 8 + 2 * (lane & 3) + (e & 1);
                float v = fmaxf(acc[mi][ni][e] + sBias[col], 0.f);
                rs[mi][e >> 1][0] = fmaf(v, sWg0[col], rs[mi][e >> 1][0]);
                rs[mi][e >> 1][1] = fmaf(v, sWg1[col], rs[mi][e >> 1][1]);
                rs[mi][e >> 1][2] = fmaf(v, sWd[col],  rs[mi][e >> 1][2]);
            }

    const int slot = nt * 2 + wn;
#pragma unroll
    for (int mi = 0; mi < 4; ++mi)
#pragma unroll
        for (int e2 = 0; e2 < 2; ++e2)
#pragma unroll
            for (int ch = 0; ch < 3; ++ch) {
                float v = rs[mi][e2][ch];
                v += __shfl_xor_sync(0xffffffffu, v, 1);
                v += __shfl_xor_sync(0xffffffffu, v, 2);
                if ((lane & 3) == 0) {
                    int row = m0 + wm * 64 + mi * 16 + (lane >> 2) + e2 * 8;
                    g_part[((size_t)ch * NSLOT + slot) * Msz + row] = v;
                }
            }
}

// ---------------------------------------------------------------------------
// finalize: combine partials -> gate, gate_next, distances (round-16 version).
// ---------------------------------------------------------------------------
__global__ void finalize_kernel(const float* __restrict__ gate2_b,
                                const float* __restrict__ dist_b,
                                float* __restrict__ out) {
    int m = blockIdx.x * blockDim.x + threadIdx.x;
    if (m >= Msz) return;
    float s0 = 0.f, s1 = 0.f, sd = 0.f;
#pragma unroll
    for (int sl = 0; sl < NSLOT; ++sl) {
        s0 += g_part[(0 * NSLOT + sl) * (size_t)Msz + m];
        s1 += g_part[(1 * NSLOT + sl) * (size_t)Msz + m];
        sd += g_part[(2 * NSLOT + sl) * (size_t)Msz + m];
    }
    int t = m >> 6, b = m & 63;
    int bt = b * T_ + t;
    float gate  = sigmf(s0 + gate2_b[0]);
    float gaten = sigmf(s1 + gate2_b[1]);
    g_gate[bt]  = gate;
    g_gaten[bt] = gaten;
    out[OFF_GATE + bt] = gate;
    out[OFF_DIST + bt] = sd + dist_b[0];
}

// ---------------------------------------------------------------------------
// mg / mgn cumprod + cum tail. Channel-split (warp-uniform channel) + smem
// store transpose: each warp stages its 32x15 results in smem, then writes
// the contiguous 480-float output span in 15 coalesced transactions.
// Same float ops per output, same order => bit-identical results.
// ---------------------------------------------------------------------------
__global__ __launch_bounds__(256)
void mg_cum_kernel(const float* __restrict__ cum_gate, float* __restrict__ out) {
    __shared__ float buf[8][32 * NSLOTS];   // 8 warps x 480 floats = 15.4 KB
    int idx = blockIdx.x * blockDim.x + threadIdx.x;
    if (idx >= 2 * B_ * T_) return;
    const int warp = threadIdx.x >> 5;
    const int lane = threadIdx.x & 31;
    int ch  = idx >> 16;               // 0 = mg, 1 = mgn (warp-uniform)
    int bt  = idx & (B_ * T_ - 1);
    int b = bt >> 10, t = bt & (T_ - 1);
    float gv = ch ? g_gaten[bt] : g_gate[bt];

    // Phase 1: independent sigmoids.
    float sv[NSLOTS];
#pragma unroll
    for (int j = 0; j < NSLOTS; ++j) {
        int s = NSLOTS - j + t;
        float gh = (s < NSLOTS) ? cum_gate[b * NSLOTS + s] : g_gate[b * T_ + (s - NSLOTS)];
        sv[j] = sigmf((gv - gh) * 100.f + 5.f);
    }

    // Phase 2: cumprod into smem tile.
    float p = 1.f;
#pragma unroll
    for (int j = 0; j < NSLOTS; ++j) {
        p *= sv[j];
        buf[warp][lane * NSLOTS + j] = p;
    }
    __syncwarp();

    // Phase 3: coalesced copy of the warp's contiguous 480-float span.
    // Warp base bt = bt - lane; output base = OFF + (bt-lane)*15.
    {
        size_t obase = (ch ? OFF_MGN : OFF_MG) + (size_t)(bt - lane) * NSLOTS;
#pragma unroll
        for (int j = 0; j < NSLOTS; ++j) {
            int q = j * 32 + lane;
            out[obase + q] = buf[warp][q];
        }
    }

    // cum[:, -15:] tail (from the ch==0 range only)
    if (idx < B_ * NSLOTS) {
        int bb = idx / NSLOTS, j = idx % NSLOTS;
        out[OFF_CUM + idx] = g_gate[bb * T_ + (T_ - NSLOTS) + j];
    }
}

extern "C" void kernel_launch(void* const* d_in, const int* in_sizes, int n_in,
                              void* d_out, int out_size) {
    const float* emb      = (const float*)d_in[0];
    const float* emb_last = (const float*)d_in[1];
    const float* cum_gate = (const float*)d_in[2];
    const float* conv1_w  = (const float*)d_in[3];
    const float* conv1_b  = (const float*)d_in[4];
    const float* bn_gamma = (const float*)d_in[5];
    const float* bn_beta  = (const float*)d_in[6];
    const float* bn_mean  = (const float*)d_in[7];
    const float* bn_var   = (const float*)d_in[8];
    const float* gate2_w  = (const float*)d_in[9];
    const float* gate2_b  = (const float*)d_in[10];
    const float* dist_w   = (const float*)d_in[11];
    const float* dist_b   = (const float*)d_in[12];
    float* out = (float*)d_out;

    cudaFuncSetAttribute(gemm_kernel, cudaFuncAttributeMaxDynamicSharedMemorySize,
                         SMEM_TOTAL);

    prep_kernel<<<PREP_BLOCKS, 256>>>(emb, emb_last, conv1_w, conv1_b, bn_gamma,
                                      bn_beta, bn_mean, bn_var, gate2_w, dist_w, out);
    gemm_kernel<<<dim3(NT, MT), 128, SMEM_TOTAL>>>();
    finalize_kernel<<<Msz / 256, 256>>>(gate2_b, dist_b, out);
    mg_cum_kernel<<<(2 * B_ * T_) / 256, 256>>>(cum_gate, out);
}